// round 2
// baseline (speedup 1.0000x reference)
#include <cuda_runtime.h>

// Shapes from reference: B=16, C=32, H1=W1=256, H2=W2=64
#define NCH   512                         // B*C
#define H1D   256
#define W1D   256
#define TW    64
#define HO    319                         // H1 + TW - 1
#define SARV  4096.0f                     // H2*W2
#define EPSV  1.1920928955078125e-07f     // float32 eps

// ---------------------------------------------------------------------------
// Probe kernel: one CTA per (channel, output row). 256 threads.
// Everything computed by direct summation — no running windows, no scans,
// no cross-kernel state. Deliberately simple to isolate correctness.
// ---------------------------------------------------------------------------
__global__ __launch_bounds__(256) void ncc_probe(const float* __restrict__ f1,
                                                 const float* __restrict__ f2,
                                                 const float* __restrict__ xcg,
                                                 float* __restrict__ outg) {
    const int c = blockIdx.y;     // channel 0..511
    const int i = blockIdx.x;     // output row 0..318
    const int t = threadIdx.x;    // 0..255

    const float* __restrict__ x  = f1  + (size_t)c * (H1D * W1D);
    const float* __restrict__ p2 = f2  + (size_t)c * (TW * TW);
    const float* __restrict__ xc = xcg + (size_t)c * (HO * HO) + (size_t)i * HO;
    float* __restrict__ op       = outg + (size_t)c * (HO * HO) + (size_t)i * HO;

    __shared__ float sred[256];

    // ---- per-channel stats of feat_2 (computed redundantly per CTA) ----
    float vals[16];
    float s = 0.f;
#pragma unroll
    for (int k = 0; k < 16; ++k) {
        vals[k] = p2[t + 256 * k];
        s += vals[k];
    }
    sred[t] = s;
    __syncthreads();
    for (int stride = 128; stride > 0; stride >>= 1) {
        if (t < stride) sred[t] += sred[t + stride];
        __syncthreads();
    }
    const float mean = sred[0] / SARV;
    __syncthreads();                    // all reads of sred[0] done before reuse

    float ss = 0.f;
#pragma unroll
    for (int k = 0; k < 16; ++k) {
        float d = vals[k] - mean;
        ss += d * d;
    }
    sred[t] = ss;
    __syncthreads();
    for (int stride = 128; stride > 0; stride >>= 1) {
        if (t < stride) sred[t] += sred[t + stride];
        __syncthreads();
    }
    const float ssd = sred[0];
    __syncthreads();

    // ---- vertical window sums per column (direct, no running trick) ----
    // Output row i covers feat_1 rows [i-63, i] ∩ [0, 255].
    __shared__ float CS[W1D];
    __shared__ float CS2[W1D];
    {
        const int rlo = max(i - (TW - 1), 0);
        const int rhi = min(i, H1D - 1);
        float v = 0.f, v2 = 0.f;
        for (int r = rlo; r <= rhi; ++r) {
            float a = x[r * W1D + t];
            v  += a;
            v2 += a * a;
        }
        CS[t]  = v;
        CS2[t] = v2;
    }
    __syncthreads();

    // ---- horizontal window + NCC epilogue (direct 64-term sums) ----
#pragma unroll
    for (int rep = 0; rep < 2; ++rep) {
        int j = t + rep * 256;
        if (j < HO) {
            const int c0 = max(j - (TW - 1), 0);
            const int c1 = min(j, W1D - 1);
            float ws = 0.f, ws2 = 0.f;
            for (int q = c0; q <= c1; ++q) {
                ws  += CS[q];
                ws2 += CS2[q];
            }
            float num = xc[j] - ws * mean;
            float wcr = ws2 - ws * ws * (1.0f / SARV);
            float den = sqrtf(fmaxf(wcr * ssd, 0.f));
            float r   = fmaxf(num, EPSV) / fmaxf(den, EPSV);
            op[j] = (den > EPSV) ? r : 0.f;
        }
    }
}

// ---------------------------------------------------------------------------
extern "C" void kernel_launch(void* const* d_in, const int* in_sizes, int n_in,
                              void* d_out, int out_size) {
    const float* feat1 = nullptr;
    const float* feat2 = nullptr;
    const float* xcorr = nullptr;
    for (int i = 0; i < n_in; ++i) {
        if (in_sizes[i] == NCH * H1D * W1D)     feat1 = (const float*)d_in[i];
        else if (in_sizes[i] == NCH * TW * TW)  feat2 = (const float*)d_in[i];
        else if (in_sizes[i] == NCH * HO * HO)  xcorr = (const float*)d_in[i];
    }
    float* out = (float*)d_out;

    dim3 grid(HO, NCH);
    ncc_probe<<<grid, 256>>>(feat1, feat2, xcorr, out);
}

// round 5
// speedup vs baseline: 3.0923x; 3.0923x over previous
#include <cuda_runtime.h>

// Shapes: B=16, C=32, H1=W1=256, H2=W2=64
#define NCH   512
#define H1D   256
#define W1D   256
#define TW    64
#define HO    319                         // H1 + TW - 1
#define SARV  4096.0f
#define EPSV  1.1920928955078125e-07f     // float32 eps

#define KROWS 16
#define NCHNK ((HO + KROWS - 1) / KROWS)  // 20

// ---------------------------------------------------------------------------
// Single fused kernel. CTA = (channel, chunk of 16 output rows), 256 threads.
// All window sums are built from IN-WINDOW elements only (no cancellation):
//   vertical  = suffix-snapshot[i-63 .. i0-1] + running-prefix[i0 .. i]
//   horizontal= per-64-col-block suffix[c0] + prefix[c1]   (van Herk)
// ---------------------------------------------------------------------------
__global__ __launch_bounds__(256) void ncc_vh(const float* __restrict__ f1,
                                              const float* __restrict__ f2,
                                              const float* __restrict__ xcg,
                                              float* __restrict__ outg) {
    const int c  = blockIdx.y;
    const int i0 = blockIdx.x * KROWS;
    const int t  = threadIdx.x;
    const int lane = t & 31;
    const int w    = t >> 5;        // warp 0..7
    const int h    = w & 1;         // half within its 64-col block

    const float* __restrict__ x  = f1  + (size_t)c * (H1D * W1D);
    const float* __restrict__ p2 = f2  + (size_t)c * (TW * TW);
    const float* __restrict__ xc = xcg + (size_t)c * (HO * HO);
    float* __restrict__ op       = outg + (size_t)c * (HO * HO);

    // ---- per-channel stats of feat_2 (R2-verified reduction, inline) ----
    __shared__ float sred[256];
    {
        float vals[16];
        float s = 0.f;
#pragma unroll
        for (int k = 0; k < 16; ++k) {
            vals[k] = p2[t + 256 * k];
            s += vals[k];
        }
        sred[t] = s;
        __syncthreads();
        for (int stride = 128; stride > 0; stride >>= 1) {
            if (t < stride) sred[t] += sred[t + stride];
            __syncthreads();
        }
        float mean_l = sred[0] / SARV;
        __syncthreads();
        float ss = 0.f;
#pragma unroll
        for (int k = 0; k < 16; ++k) {
            float d = vals[k] - mean_l;
            ss += d * d;
        }
        sred[t] = ss;
        __syncthreads();
        for (int stride = 128; stride > 0; stride >>= 1) {
            if (t < stride) sred[t] += sred[t + stride];
            __syncthreads();
        }
        // leave mean in a register; ssd read below after barrier
        sred[255] = sred[0];   // keep ssd at a stable slot (t==0 wrote sred[0])
        // NOTE: all threads computed mean_l identically; stash it:
        if (t == 0) sred[254] = mean_l;
        __syncthreads();
    }
    const float mean = sred[254];
    const float ssd  = sred[255];
    __syncthreads();

    // ---- vertical suffix snapshots over rows [i0-63, i0-1] (add-only) ----
    __shared__ float snapS [KROWS][256];
    __shared__ float snapS2[KROWS][256];
    {
        float SA = 0.f, SA2 = 0.f;
        const int rtop = min(i0 - 1, H1D - 1);
        const int rbot = max(i0 - 63, 0);
        for (int r = rtop; r >= rbot; --r) {
            float a = x[r * W1D + t];
            SA  += a;
            SA2 += a * a;
            int k = r - (i0 - 63);
            if (k < KROWS) { snapS[k][t] = SA; snapS2[k][t] = SA2; }
        }
        // rows i = i0+k with i-63 < 0: lower part = [0, i0-1] = full accum
        int nfill = min(63 - i0, KROWS);
        for (int k = 0; k < nfill; ++k) { snapS[k][t] = SA; snapS2[k][t] = SA2; }
    }

    __shared__ float wtot[8], wtot2[8];
    __shared__ float Pv[256], Pv2[256], Sv[256], Sv2[256];

    float PB = 0.f, PB2 = 0.f;     // running prefix over rows [i0, i] (add-only)

    for (int k = 0; k < KROWS; ++k) {
        const int i = i0 + k;
        if (i >= HO) break;

        if (i < H1D) {
            float a = x[i * W1D + t];
            PB  += a;
            PB2 += a * a;
        }
        const float V  = snapS [k][t] + PB;    // own column, own writes
        const float V2 = snapS2[k][t] + PB2;

        // warp-inclusive prefix scans
        float p = V, pp2 = V2;
#pragma unroll
        for (int d = 1; d < 32; d <<= 1) {
            float a = __shfl_up_sync(0xffffffffu, p,   d);
            float b = __shfl_up_sync(0xffffffffu, pp2, d);
            if (lane >= d) { p += a; pp2 += b; }
        }
        // warp-inclusive suffix scans
        float s = V, s2 = V2;
#pragma unroll
        for (int d = 1; d < 32; d <<= 1) {
            float a = __shfl_down_sync(0xffffffffu, s,  d);
            float b = __shfl_down_sync(0xffffffffu, s2, d);
            if (lane + d < 32) { s += a; s2 += b; }
        }
        // cross-warp stitch within each 64-col block (warps 2b, 2b+1)
        if (lane == 31) { wtot[w] = p; wtot2[w] = pp2; }   // warp totals
        __syncthreads();
        if (h == 1) { p += wtot[w - 1]; pp2 += wtot2[w - 1]; }
        else        { s += wtot[w + 1]; s2  += wtot2[w + 1]; }

        Pv[t] = p;  Pv2[t] = pp2;
        Sv[t] = s;  Sv2[t] = s2;
        __syncthreads();

        // ---- NCC epilogue: output columns j = t and j = t + 256 ----
#pragma unroll
        for (int rep = 0; rep < 2; ++rep) {
            int j = t + rep * 256;
            if (j < HO) {
                const int c0 = max(j - (TW - 1), 0);
                const int c1 = min(j, W1D - 1);
                const int b0 = c0 >> 6;
                const int b1 = c1 >> 6;
                float ws, ws2;
                if (b0 == b1) {
                    if ((c0 & 63) == 0) { ws = Pv[c1]; ws2 = Pv2[c1]; }
                    else                { ws = Sv[c0]; ws2 = Sv2[c0]; }
                } else {
                    ws  = Sv[c0]  + Pv[c1];
                    ws2 = Sv2[c0] + Pv2[c1];
                }
                float num = xc[i * HO + j] - ws * mean;
                float wcr = ws2 - ws * ws * (1.0f / SARV);
                float den = sqrtf(fmaxf(wcr * ssd, 0.f));
                float r   = fmaxf(num, EPSV) / fmaxf(den, EPSV);
                op[i * HO + j] = (den > EPSV) ? r : 0.f;
            }
        }
        __syncthreads();   // fence epilogue reads before next row's writes
    }
}

// ---------------------------------------------------------------------------
extern "C" void kernel_launch(void* const* d_in, const int* in_sizes, int n_in,
                              void* d_out, int out_size) {
    const float* feat1 = nullptr;
    const float* feat2 = nullptr;
    const float* xcorr = nullptr;
    for (int i = 0; i < n_in; ++i) {
        if (in_sizes[i] == NCH * H1D * W1D)     feat1 = (const float*)d_in[i];
        else if (in_sizes[i] == NCH * TW * TW)  feat2 = (const float*)d_in[i];
        else if (in_sizes[i] == NCH * HO * HO)  xcorr = (const float*)d_in[i];
    }
    float* out = (float*)d_out;

    dim3 grid(NCHNK, NCH);
    ncc_vh<<<grid, 256>>>(feat1, feat2, xcorr, out);
}

// round 6
// speedup vs baseline: 4.5045x; 1.4567x over previous
#include <cuda_runtime.h>

// Shapes: B=16, C=32, H1=W1=256, H2=W2=64
#define NCH   512
#define H1D   256
#define W1D   256
#define TW    64
#define HO    319                         // H1 + TW - 1
#define SARV  4096.0f
#define EPSV  1.1920928955078125e-07f     // float32 eps

#define KROWS 16
#define NCHNK ((HO + KROWS - 1) / KROWS)  // 20

// ---------------------------------------------------------------------------
// CTA = (channel, chunk of 16 output rows), 256 threads, 2 rows per iteration.
// All window sums built from IN-WINDOW elements only (verified numerics):
//   vertical  = suffix-snapshot[i-63 .. i0-1] + running-prefix[i0 .. i]
//   horizontal= per-64-col-block suffix[c0] + prefix[c1]   (van Herk)
// ---------------------------------------------------------------------------
__global__ __launch_bounds__(256) void ncc_vh2(const float* __restrict__ f1,
                                               const float* __restrict__ f2,
                                               const float* __restrict__ xcg,
                                               float* __restrict__ outg) {
    const int c  = blockIdx.y;
    const int i0 = blockIdx.x * KROWS;
    const int t  = threadIdx.x;
    const int lane = t & 31;
    const int w    = t >> 5;        // warp 0..7
    const int h    = w & 1;         // half within its 64-col block

    const float* __restrict__ x  = f1  + (size_t)c * (H1D * W1D);
    const float* __restrict__ p2 = f2  + (size_t)c * (TW * TW);
    const float* __restrict__ xc = xcg + (size_t)c * (HO * HO);
    float* __restrict__ op       = outg + (size_t)c * (HO * HO);

    __shared__ float sred[256];
    __shared__ float snapS [KROWS][256];
    __shared__ float snapS2[KROWS][256];
    __shared__ float wtA[8], wtA2[8], wtB[8], wtB2[8];
    __shared__ float PvA[256], PvA2[256], SvA[256], SvA2[256];
    __shared__ float PvB[256], PvB2[256], SvB[256], SvB2[256];

    // ---- per-channel stats of feat_2 (verified reduction) ----
    {
        float vals[16];
        float s = 0.f;
#pragma unroll
        for (int k = 0; k < 16; ++k) {
            vals[k] = p2[t + 256 * k];
            s += vals[k];
        }
        sred[t] = s;
        __syncthreads();
        for (int stride = 128; stride > 0; stride >>= 1) {
            if (t < stride) sred[t] += sred[t + stride];
            __syncthreads();
        }
        float mean_l = sred[0] / SARV;
        __syncthreads();
        float ss = 0.f;
#pragma unroll
        for (int k = 0; k < 16; ++k) {
            float d = vals[k] - mean_l;
            ss += d * d;
        }
        sred[t] = ss;
        __syncthreads();
        for (int stride = 128; stride > 0; stride >>= 1) {
            if (t < stride) sred[t] += sred[t + stride];
            __syncthreads();
        }
        sred[255] = sred[0];
        if (t == 0) sred[254] = mean_l;
        __syncthreads();
    }
    const float mean = sred[254];
    const float ssd  = sred[255];
    __syncthreads();

    // ---- vertical suffix snapshots over rows [i0-63, i0-1] (add-only) ----
    {
        float SA = 0.f, SA2 = 0.f;
        const int rtop = min(i0 - 1, H1D - 1);
        const int rbot = max(i0 - 63, 0);
        for (int r = rtop; r >= rbot; --r) {
            float a = x[r * W1D + t];
            SA  += a;
            SA2 += a * a;
            int k = r - (i0 - 63);
            if (k < KROWS) { snapS[k][t] = SA; snapS2[k][t] = SA2; }
        }
        int nfill = min(63 - i0, KROWS);
        for (int k = 0; k < nfill; ++k) { snapS[k][t] = SA; snapS2[k][t] = SA2; }
    }

    float PB = 0.f, PB2 = 0.f;   // running prefix over rows [i0, i] (add-only)

    for (int kk = 0; kk < KROWS / 2; ++kk) {
        const int ia = i0 + 2 * kk;
        const int ib = ia + 1;
        const bool bvalid = (ib < HO);

        // --- issue all global loads for this iteration up front (MLP) ---
        float la = 0.f, lb = 0.f;
        if (ia < H1D) la = x[ia * W1D + t];
        if (ib < H1D) lb = x[ib * W1D + t];
        float xa0 = xc[(size_t)ia * HO + t];
        float xa1 = (t < HO - 256) ? xc[(size_t)ia * HO + 256 + t] : 0.f;
        float xb0 = 0.f, xb1 = 0.f;
        if (bvalid) {
            xb0 = xc[(size_t)ib * HO + t];
            xb1 = (t < HO - 256) ? xc[(size_t)ib * HO + 256 + t] : 0.f;
        }

        // --- vertical windows for both rows ---
        PB  += la;
        PB2 += la * la;
        const float Va  = snapS [2 * kk][t] + PB;
        const float V2a = snapS2[2 * kk][t] + PB2;
        PB  += lb;
        PB2 += lb * lb;
        const float Vb  = snapS [2 * kk + 1][t] + PB;
        const float V2b = snapS2[2 * kk + 1][t] + PB2;

        // --- warp prefix scans (4 independent chains) ---
        float pa = Va, pa2 = V2a, pb = Vb, pb2 = V2b;
#pragma unroll
        for (int d = 1; d < 32; d <<= 1) {
            float u0 = __shfl_up_sync(0xffffffffu, pa,  d);
            float u1 = __shfl_up_sync(0xffffffffu, pa2, d);
            float u2 = __shfl_up_sync(0xffffffffu, pb,  d);
            float u3 = __shfl_up_sync(0xffffffffu, pb2, d);
            if (lane >= d) { pa += u0; pa2 += u1; pb += u2; pb2 += u3; }
        }
        // --- warp suffix scans ---
        float sa = Va, sa2 = V2a, sb = Vb, sb2 = V2b;
#pragma unroll
        for (int d = 1; d < 32; d <<= 1) {
            float u0 = __shfl_down_sync(0xffffffffu, sa,  d);
            float u1 = __shfl_down_sync(0xffffffffu, sa2, d);
            float u2 = __shfl_down_sync(0xffffffffu, sb,  d);
            float u3 = __shfl_down_sync(0xffffffffu, sb2, d);
            if (lane + d < 32) { sa += u0; sa2 += u1; sb += u2; sb2 += u3; }
        }

        // warp totals (prefix at lane 31 == warp sum, serves both stitches)
        if (lane == 31) { wtA[w] = pa; wtA2[w] = pa2; wtB[w] = pb; wtB2[w] = pb2; }
        __syncthreads();
        if (h == 1) {
            pa += wtA[w - 1]; pa2 += wtA2[w - 1];
            pb += wtB[w - 1]; pb2 += wtB2[w - 1];
        } else {
            sa += wtA[w + 1]; sa2 += wtA2[w + 1];
            sb += wtB[w + 1]; sb2 += wtB2[w + 1];
        }
        PvA[t] = pa; PvA2[t] = pa2; SvA[t] = sa; SvA2[t] = sa2;
        PvB[t] = pb; PvB2[t] = pb2; SvB[t] = sb; SvB2[t] = sb2;
        __syncthreads();

        // --- epilogue ---
        // rep0: j = t. Window pure-prefix iff t<=63 or (t&63)==63; else Sv+Pv.
        const bool addS = (t > 63) && ((t & 63) != 63);
        const int  cs   = max(t - 63, 0);
        {
            float ws  = PvA[t]  + (addS ? SvA[cs]  : 0.f);
            float ws2 = PvA2[t] + (addS ? SvA2[cs] : 0.f);
            float num = xa0 - ws * mean;
            float wcr = ws2 - ws * ws * (1.0f / SARV);
            float den = sqrtf(fmaxf(wcr * ssd, 0.f));
            float r   = fmaxf(num, EPSV) / fmaxf(den, EPSV);
            op[(size_t)ia * HO + t] = (den > EPSV) ? r : 0.f;
        }
        if (bvalid) {
            float ws  = PvB[t]  + (addS ? SvB[cs]  : 0.f);
            float ws2 = PvB2[t] + (addS ? SvB2[cs] : 0.f);
            float num = xb0 - ws * mean;
            float wcr = ws2 - ws * ws * (1.0f / SARV);
            float den = sqrtf(fmaxf(wcr * ssd, 0.f));
            float r   = fmaxf(num, EPSV) / fmaxf(den, EPSV);
            op[(size_t)ib * HO + t] = (den > EPSV) ? r : 0.f;
        }
        // rep1: j = t + 256 (valid iff t < 63). Always pure suffix: Sv[t+193].
        if (t < HO - 256) {
            {
                float ws  = SvA[t + 193];
                float ws2 = SvA2[t + 193];
                float num = xa1 - ws * mean;
                float wcr = ws2 - ws * ws * (1.0f / SARV);
                float den = sqrtf(fmaxf(wcr * ssd, 0.f));
                float r   = fmaxf(num, EPSV) / fmaxf(den, EPSV);
                op[(size_t)ia * HO + 256 + t] = (den > EPSV) ? r : 0.f;
            }
            if (bvalid) {
                float ws  = SvB[t + 193];
                float ws2 = SvB2[t + 193];
                float num = xb1 - ws * mean;
                float wcr = ws2 - ws * ws * (1.0f / SARV);
                float den = sqrtf(fmaxf(wcr * ssd, 0.f));
                float r   = fmaxf(num, EPSV) / fmaxf(den, EPSV);
                op[(size_t)ib * HO + 256 + t] = (den > EPSV) ? r : 0.f;
            }
        }
        __syncthreads();   // fence epilogue reads before next iteration's writes
    }
}

// ---------------------------------------------------------------------------
extern "C" void kernel_launch(void* const* d_in, const int* in_sizes, int n_in,
                              void* d_out, int out_size) {
    const float* feat1 = nullptr;
    const float* feat2 = nullptr;
    const float* xcorr = nullptr;
    for (int i = 0; i < n_in; ++i) {
        if (in_sizes[i] == NCH * H1D * W1D)     feat1 = (const float*)d_in[i];
        else if (in_sizes[i] == NCH * TW * TW)  feat2 = (const float*)d_in[i];
        else if (in_sizes[i] == NCH * HO * HO)  xcorr = (const float*)d_in[i];
    }
    float* out = (float*)d_out;

    dim3 grid(NCHNK, NCH);
    ncc_vh2<<<grid, 256>>>(feat1, feat2, xcorr, out);
}

// round 7
// speedup vs baseline: 5.2269x; 1.1604x over previous
#include <cuda_runtime.h>

// Shapes: B=16, C=32, H1=W1=256, H2=W2=64
#define NCH   512
#define H1D   256
#define W1D   256
#define TW    64
#define HO    319                         // H1 + TW - 1
#define SARV  4096.0f
#define EPSV  1.1920928955078125e-07f     // float32 eps

#define KROWS 16
#define NCHNK ((HO + KROWS - 1) / KROWS)  // 20

// ---------------------------------------------------------------------------
// CTA = (channel, chunk of 16 output rows), 256 threads, 2 rows per iteration.
// In-window-only sums (verified numerics). Suffix within a warp is obtained by
// (warp_total - prefix) + own, which is cancellation-safe at warp scope and
// bit-exact at the extreme lane. Prefix stays in registers (epilogue j=t uses
// the thread's own prefix); only suffixes are published to smem.
// ---------------------------------------------------------------------------
__global__ __launch_bounds__(256) void ncc_vh3(const float* __restrict__ f1,
                                               const float* __restrict__ f2,
                                               const float* __restrict__ xcg,
                                               float* __restrict__ outg) {
    const int c  = blockIdx.y;
    const int i0 = blockIdx.x * KROWS;
    const int t  = threadIdx.x;
    const int lane = t & 31;
    const int w    = t >> 5;        // warp 0..7
    const int h    = w & 1;         // half within its 64-col block

    const float* __restrict__ x  = f1  + (size_t)c * (H1D * W1D);
    const float* __restrict__ p2 = f2  + (size_t)c * (TW * TW);
    const float* __restrict__ xc = xcg + (size_t)c * (HO * HO);
    float* __restrict__ op       = outg + (size_t)c * (HO * HO);

    __shared__ float  sred[256];
    __shared__ float2 snap[KROWS][256];          // vertical suffix snapshots (S, S2)
    __shared__ float4 wtot4[8];                  // per-warp totals (A,A2,B,B2)
    __shared__ float2 SvA[256], SvB[256];        // published 64-block suffixes

    // ---- per-channel stats of feat_2 (verified reduction) ----
    float mean, ssd;
    {
        float vals[16];
        float s = 0.f;
#pragma unroll
        for (int k = 0; k < 16; ++k) {
            vals[k] = p2[t + 256 * k];
            s += vals[k];
        }
        sred[t] = s;
        __syncthreads();
        for (int stride = 128; stride > 0; stride >>= 1) {
            if (t < stride) sred[t] += sred[t + stride];
            __syncthreads();
        }
        mean = sred[0] / SARV;                   // identical on all threads
        __syncthreads();
        float ss = 0.f;
#pragma unroll
        for (int k = 0; k < 16; ++k) {
            float d = vals[k] - mean;
            ss += d * d;
        }
        sred[t] = ss;
        __syncthreads();
        for (int stride = 128; stride > 0; stride >>= 1) {
            if (t < stride) sred[t] += sred[t + stride];
            __syncthreads();
        }
        ssd = sred[0];
        __syncthreads();
    }

    // ---- vertical suffix snapshots over rows [i0-63, i0-1] (add-only) ----
    {
        float SA = 0.f, SA2 = 0.f;
        const int rtop = min(i0 - 1, H1D - 1);
        const int rbot = max(i0 - 63, 0);
        for (int r = rtop; r >= rbot; --r) {
            float a = x[r * W1D + t];
            SA  += a;
            SA2 += a * a;
            int k = r - (i0 - 63);
            if (k < KROWS) snap[k][t] = make_float2(SA, SA2);
        }
        int nfill = min(63 - i0, KROWS);
        for (int k = 0; k < nfill; ++k) snap[k][t] = make_float2(SA, SA2);
        for (int k = max(HO - i0, 0); k < KROWS; ++k)    // unused tail rows
            snap[k][t] = make_float2(0.f, 0.f);
    }
    // snapshots are read only by the same thread that wrote them -> no barrier

    float PB = 0.f, PB2 = 0.f;   // running prefix over rows [i0, i] (add-only)

    for (int kk = 0; kk < KROWS / 2; ++kk) {
        const int ia = i0 + 2 * kk;
        const int ib = ia + 1;
        const bool bvalid = (ib < HO);

        // --- all global loads for this iteration up front (MLP) ---
        float la = 0.f, lb = 0.f;
        if (ia < H1D) la = x[ia * W1D + t];
        if (ib < H1D) lb = x[ib * W1D + t];
        float xa0 = xc[(size_t)ia * HO + t];
        float xa1 = (t < HO - 256) ? xc[(size_t)ia * HO + 256 + t] : 0.f;
        float xb0 = 0.f, xb1 = 0.f;
        if (bvalid) {
            xb0 = xc[(size_t)ib * HO + t];
            xb1 = (t < HO - 256) ? xc[(size_t)ib * HO + 256 + t] : 0.f;
        }

        // --- vertical windows for both rows ---
        PB  += la;
        PB2 += la * la;
        float2 sn = snap[2 * kk][t];
        const float Va  = sn.x + PB;
        const float V2a = sn.y + PB2;
        PB  += lb;
        PB2 += lb * lb;
        sn = snap[2 * kk + 1][t];
        const float Vb  = sn.x + PB;
        const float V2b = sn.y + PB2;

        // --- warp prefix scans (4 independent chains) ---
        float pa = Va, pa2 = V2a, pb = Vb, pb2 = V2b;
#pragma unroll
        for (int d = 1; d < 32; d <<= 1) {
            float u0 = __shfl_up_sync(0xffffffffu, pa,  d);
            float u1 = __shfl_up_sync(0xffffffffu, pa2, d);
            float u2 = __shfl_up_sync(0xffffffffu, pb,  d);
            float u3 = __shfl_up_sync(0xffffffffu, pb2, d);
            if (lane >= d) { pa += u0; pa2 += u1; pb += u2; pb2 += u3; }
        }
        // warp totals (broadcast lane 31)
        const float totA  = __shfl_sync(0xffffffffu, pa,  31);
        const float totA2 = __shfl_sync(0xffffffffu, pa2, 31);
        const float totB  = __shfl_sync(0xffffffffu, pb,  31);
        const float totB2 = __shfl_sync(0xffffffffu, pb2, 31);
        // warp suffixes via cancellation-safe subtraction (exact at lane 31)
        float sa  = (totA  - pa)  + Va;
        float sa2 = (totA2 - pa2) + V2a;
        float sb  = (totB  - pb)  + Vb;
        float sb2 = (totB2 - pb2) + V2b;

        if (lane == 0) wtot4[w] = make_float4(totA, totA2, totB, totB2);
        __syncthreads();

        // stitch 64-col blocks (warps 2b, 2b+1)
        if (h == 1) {
            float4 q = wtot4[w - 1];
            pa += q.x; pa2 += q.y; pb += q.z; pb2 += q.w;
        } else {
            float4 q = wtot4[w + 1];
            sa += q.x; sa2 += q.y; sb += q.z; sb2 += q.w;
        }
        SvA[t] = make_float2(sa, sa2);
        SvB[t] = make_float2(sb, sb2);
        __syncthreads();

        // --- epilogue ---
        // j = t: window = own prefix (+ suffix piece when straddling blocks)
        const bool addS = (t > 63) && ((t & 63) != 63);
        {
            float ws = pa, ws2 = pa2;
            if (addS) { float2 q = SvA[t - 63]; ws += q.x; ws2 += q.y; }
            float num = xa0 - ws * mean;
            float wcr = ws2 - ws * ws * (1.0f / SARV);
            float den = sqrtf(fmaxf(wcr * ssd, 0.f));
            float r   = fmaxf(num, EPSV) / fmaxf(den, EPSV);
            op[(size_t)ia * HO + t] = (den > EPSV) ? r : 0.f;
        }
        if (bvalid) {
            float ws = pb, ws2 = pb2;
            if (addS) { float2 q = SvB[t - 63]; ws += q.x; ws2 += q.y; }
            float num = xb0 - ws * mean;
            float wcr = ws2 - ws * ws * (1.0f / SARV);
            float den = sqrtf(fmaxf(wcr * ssd, 0.f));
            float r   = fmaxf(num, EPSV) / fmaxf(den, EPSV);
            op[(size_t)ib * HO + t] = (den > EPSV) ? r : 0.f;
        }
        // j = t + 256 (t < 63): always pure suffix Sv[t + 193]
        if (t < HO - 256) {
            {
                float2 q = SvA[t + 193];
                float num = xa1 - q.x * mean;
                float wcr = q.y - q.x * q.x * (1.0f / SARV);
                float den = sqrtf(fmaxf(wcr * ssd, 0.f));
                float r   = fmaxf(num, EPSV) / fmaxf(den, EPSV);
                op[(size_t)ia * HO + 256 + t] = (den > EPSV) ? r : 0.f;
            }
            if (bvalid) {
                float2 q = SvB[t + 193];
                float num = xb1 - q.x * mean;
                float wcr = q.y - q.x * q.x * (1.0f / SARV);
                float den = sqrtf(fmaxf(wcr * ssd, 0.f));
                float r   = fmaxf(num, EPSV) / fmaxf(den, EPSV);
                op[(size_t)ib * HO + 256 + t] = (den > EPSV) ? r : 0.f;
            }
        }
        // next iteration's wtot4/Sv writes are separated from this epilogue's
        // reads by the __syncthreads after the wtot4 store above.
    }
}

// ---------------------------------------------------------------------------
extern "C" void kernel_launch(void* const* d_in, const int* in_sizes, int n_in,
                              void* d_out, int out_size) {
    const float* feat1 = nullptr;
    const float* feat2 = nullptr;
    const float* xcorr = nullptr;
    for (int i = 0; i < n_in; ++i) {
        if (in_sizes[i] == NCH * H1D * W1D)     feat1 = (const float*)d_in[i];
        else if (in_sizes[i] == NCH * TW * TW)  feat2 = (const float*)d_in[i];
        else if (in_sizes[i] == NCH * HO * HO)  xcorr = (const float*)d_in[i];
    }
    float* out = (float*)d_out;

    dim3 grid(NCHNK, NCH);
    ncc_vh3<<<grid, 256>>>(feat1, feat2, xcorr, out);
}